// round 1
// baseline (speedup 1.0000x reference)
#include <cuda_runtime.h>
#include <cuda_bf16.h>
#include <math.h>

#define NN  50000
#define EE  800000
#define INC 512
#define HH  64
#define OC  40
#define NL  64

// ---------------- device scratch (static, no allocation) ----------------
__device__ float g_dinv[NN];
__device__ int   g_cnt[NN];
__device__ int   g_rowptr[NN + 1];
__device__ int   g_fill[NN];
__device__ int   g_col[EE];
__device__ float g_val[EE];
__device__ float g_x0[NN * HH];
__device__ float g_hbuf[2][NN * HH];
__device__ int   g_is64;

// ---------------- preprocessing ----------------
__global__ void k_zero_cnt() {
    int i = blockIdx.x * blockDim.x + threadIdx.x;
    if (i < NN) g_cnt[i] = 0;
}

// Detect whether edge_index is int64 or int32: if int64 (values < 2^31),
// every odd 32-bit word of the first 64 entries is 0.
__global__ void k_detect(const int* ei32) {
    if (threadIdx.x == 0 && blockIdx.x == 0) {
        int all0 = 1;
        for (int i = 0; i < 64; i++)
            if (ei32[2 * i + 1] != 0) all0 = 0;
        g_is64 = all0;
    }
}

__global__ void k_count(const void* eiv) {
    int e = blockIdx.x * blockDim.x + threadIdx.x;
    if (e >= EE) return;
    int d;
    if (g_is64) d = (int)((const long long*)eiv)[EE + e];
    else        d = ((const int*)eiv)[EE + e];
    atomicAdd(&g_cnt[d], 1);
}

// Single-block exclusive scan over 50000 counts; also deg->dinv, zero fill.
__global__ void k_scan() {
    __shared__ int part[1024];
    const int T = 1024;
    const int IT = (NN + T - 1) / T;  // 49
    int t = threadIdx.x;
    int base = t * IT;
    int s = 0;
    for (int i = 0; i < IT; i++) {
        int idx = base + i;
        if (idx < NN) s += g_cnt[idx];
    }
    part[t] = s;
    __syncthreads();
    for (int off = 1; off < T; off <<= 1) {
        int v = (t >= off) ? part[t - off] : 0;
        __syncthreads();
        part[t] += v;
        __syncthreads();
    }
    int run = part[t] - s;  // exclusive
    for (int i = 0; i < IT; i++) {
        int idx = base + i;
        if (idx < NN) {
            g_rowptr[idx] = run;
            int c = g_cnt[idx];
            run += c;
            g_dinv[idx] = rsqrtf((float)(c + 1));  // +1 self loop
            g_fill[idx] = 0;
        }
    }
    if (t == T - 1) g_rowptr[NN] = run;  // == EE
}

__global__ void k_fill(const void* eiv) {
    int e = blockIdx.x * blockDim.x + threadIdx.x;
    if (e >= EE) return;
    int s, d;
    if (g_is64) {
        const long long* ei = (const long long*)eiv;
        s = (int)ei[e];
        d = (int)ei[EE + e];
    } else {
        const int* ei = (const int*)eiv;
        s = ei[e];
        d = ei[EE + e];
    }
    int pos = g_rowptr[d] + atomicAdd(&g_fill[d], 1);
    g_col[pos] = s;
    g_val[pos] = g_dinv[s] * g_dinv[d];
}

// ---------------- lin1: h = relu(x @ W1 + b1), write x0 and hbuf[0] ----------------
// Block: 256 threads, 256 nodes. K tiled by 32. x staged transposed in smem.
__global__ __launch_bounds__(256) void k_lin1(const float* __restrict__ x,
                                              const float* __restrict__ w1,
                                              const float* __restrict__ b1) {
    __shared__ float xsT[32][257];
    __shared__ float ws[32 * 64];
    int t = threadIdx.x;
    int node0 = blockIdx.x * 256;

    float acc[64];
#pragma unroll
    for (int c = 0; c < 64; c++) acc[c] = 0.f;

    for (int kt = 0; kt < INC; kt += 32) {
        // W tile: 32x64
        for (int i = t; i < 32 * 64; i += 256)
            ws[i] = w1[(kt + (i >> 6)) * 64 + (i & 63)];
        // x tile transposed: 256 rows x 32 cols (2048 float4, 8/thread)
        for (int i = t; i < 2048; i += 256) {
            int r = i >> 3, c4 = i & 7;
            int node = node0 + r;
            float4 v = make_float4(0.f, 0.f, 0.f, 0.f);
            if (node < NN)
                v = *(const float4*)&x[(size_t)node * INC + kt + c4 * 4];
            xsT[c4 * 4 + 0][r] = v.x;
            xsT[c4 * 4 + 1][r] = v.y;
            xsT[c4 * 4 + 2][r] = v.z;
            xsT[c4 * 4 + 3][r] = v.w;
        }
        __syncthreads();
#pragma unroll 4
        for (int k = 0; k < 32; k++) {
            float xv = xsT[k][t];
            const float4* wr = (const float4*)&ws[k * 64];
#pragma unroll
            for (int c4 = 0; c4 < 16; c4++) {
                float4 w4 = wr[c4];
                acc[c4 * 4 + 0] += xv * w4.x;
                acc[c4 * 4 + 1] += xv * w4.y;
                acc[c4 * 4 + 2] += xv * w4.z;
                acc[c4 * 4 + 3] += xv * w4.w;
            }
        }
        __syncthreads();
    }
    int node = node0 + t;
    if (node < NN) {
#pragma unroll
        for (int c = 0; c < 64; c++) {
            float v = fmaxf(acc[c] + b1[c], 0.f);
            g_x0[node * 64 + c] = v;
            g_hbuf[0][node * 64 + c] = v;
        }
    }
}

// ---------------- fused GCNII layer ----------------
// warp-per-node: agg (CSR gather) -> residual -> z@W (W in smem) -> relu
__global__ __launch_bounds__(256) void k_layer(const float* __restrict__ W,
                                               float beta, int p) {
    __shared__ float ws[64 * 64];
    __shared__ float zsm[8][64];
    int t = threadIdx.x, w = t >> 5, lane = t & 31;
    for (int i = t; i < 4096; i += 256) ws[i] = W[i];
    __syncthreads();

    const float* hin = g_hbuf[p];
    float* hout = g_hbuf[p ^ 1];
    int warpG = blockIdx.x * 8 + w;
    int nW = gridDim.x * 8;

    for (int node = warpG; node < NN; node += nW) {
        float di = g_dinv[node];
        float2 hme = *(const float2*)&hin[node * 64 + lane * 2];
        float a0 = di * di * hme.x;
        float a1 = di * di * hme.y;
        int e0 = g_rowptr[node], e1 = g_rowptr[node + 1];
        for (int eb = e0; eb < e1; eb += 32) {
            int ee = eb + lane;
            int c = (ee < e1) ? g_col[ee] : 0;
            float v = (ee < e1) ? g_val[ee] : 0.f;
            int cnt = min(32, e1 - eb);
            for (int j = 0; j < cnt; j++) {
                int src = __shfl_sync(0xffffffffu, c, j);
                float vv = __shfl_sync(0xffffffffu, v, j);
                float2 hs = *(const float2*)&hin[src * 64 + lane * 2];
                a0 += vv * hs.x;
                a1 += vv * hs.y;
            }
        }
        float2 x02 = *(const float2*)&g_x0[node * 64 + lane * 2];
        float z0 = 0.5f * a0 + 0.5f * x02.x;
        float z1 = 0.5f * a1 + 0.5f * x02.y;
        *(float2*)&zsm[w][lane * 2] = make_float2(z0, z1);
        __syncwarp();
        float s0 = 0.f, s1 = 0.f;
#pragma unroll
        for (int k = 0; k < 64; k++) {
            float zk = zsm[w][k];
            float2 w2 = *(const float2*)&ws[k * 64 + lane * 2];
            s0 += zk * w2.x;
            s1 += zk * w2.y;
        }
        float ob = 1.f - beta;
        float o0 = fmaxf(ob * z0 + beta * s0, 0.f);
        float o1 = fmaxf(ob * z1 + beta * s1, 0.f);
        *(float2*)&hout[node * 64 + lane * 2] = make_float2(o0, o1);
        __syncwarp();
    }
}

// ---------------- output: lin2 + log_softmax ----------------
__global__ __launch_bounds__(256) void k_out(const float* __restrict__ w2,
                                             const float* __restrict__ b2,
                                             float* __restrict__ out) {
    __shared__ float ws[64 * OC];
    __shared__ float bs[OC];
    __shared__ float zsm[8][64];
    int t = threadIdx.x, w = t >> 5, lane = t & 31;
    for (int i = t; i < 64 * OC; i += 256) ws[i] = w2[i];
    if (t < OC) bs[t] = b2[t];
    __syncthreads();

    const float* h = g_hbuf[0];  // NL even -> final state in buffer 0
    int warpG = blockIdx.x * 8 + w;
    int nW = gridDim.x * 8;

    for (int node = warpG; node < NN; node += nW) {
        float2 h2 = *(const float2*)&h[node * 64 + lane * 2];
        *(float2*)&zsm[w][lane * 2] = h2;
        __syncwarp();
        int c0 = lane;            // always < 40
        int c1 = lane + 32;       // valid if lane < 8
        float v0 = bs[c0];
        float v1 = (lane < 8) ? bs[c1] : 0.f;
#pragma unroll
        for (int k = 0; k < 64; k++) {
            float zk = zsm[w][k];
            v0 += zk * ws[k * OC + c0];
            if (lane < 8) v1 += zk * ws[k * OC + c1];
        }
        float m = v0;
        if (lane < 8) m = fmaxf(m, v1);
#pragma unroll
        for (int o = 16; o > 0; o >>= 1)
            m = fmaxf(m, __shfl_xor_sync(0xffffffffu, m, o));
        float se = expf(v0 - m) + ((lane < 8) ? expf(v1 - m) : 0.f);
#pragma unroll
        for (int o = 16; o > 0; o >>= 1)
            se += __shfl_xor_sync(0xffffffffu, se, o);
        float lse = m + logf(se);
        out[node * OC + c0] = v0 - lse;
        if (lane < 8) out[node * OC + c1] = v1 - lse;
        __syncwarp();
    }
}

// ---------------- launch ----------------
extern "C" void kernel_launch(void* const* d_in, const int* in_sizes, int n_in,
                              void* d_out, int out_size) {
    (void)in_sizes; (void)n_in; (void)out_size;
    const float* x  = (const float*)d_in[0];
    const void*  ei = d_in[1];
    const float* w1 = (const float*)d_in[2];
    const float* b1 = (const float*)d_in[3];
    const float* cw = (const float*)d_in[4];
    const float* w2 = (const float*)d_in[5];
    const float* b2 = (const float*)d_in[6];
    float* out = (float*)d_out;

    k_zero_cnt<<<(NN + 1023) / 1024, 1024>>>();
    k_detect<<<1, 32>>>((const int*)ei);
    k_count<<<(EE + 255) / 256, 256>>>(ei);
    k_scan<<<1, 1024>>>();
    k_fill<<<(EE + 255) / 256, 256>>>(ei);
    k_lin1<<<(NN + 255) / 256, 256>>>(x, w1, b1);

    for (int l = 0; l < NL; l++) {
        float beta = logf(1.0f / (float)(l + 1) + 1.0f);
        k_layer<<<1024, 256>>>(cw + (size_t)l * HH * HH, beta, l & 1);
    }
    k_out<<<512, 256>>>(w2, b2, out);
}